// round 1
// baseline (speedup 1.0000x reference)
#include <cuda_runtime.h>
#include <math.h>

#define NN 100000
#define NE 1600000
#define DH 128
#define DO 64

// ---- scratch (static device globals; no allocation allowed) ----
__device__ float g_h   [(size_t)NN * DH];   // layer1 pre-agg / layer1 activated output
__device__ float g_h2  [(size_t)NN * DO];   // layer2 pre-agg
__device__ float g_agg [(size_t)NN * DH];   // aggregation buffer (reused for layer2, 64-dim)
__device__ float g_dinv[NN];
__device__ int   g_deg [NN];
__device__ int   g_src [NE];
__device__ int   g_dst [NE];
__device__ float g_norm[NE];
__device__ unsigned g_odd_or;               // dtype detection: 0 => edge_index is int64

// ---------------------------------------------------------------
__global__ void k_init() {
    int i = blockIdx.x * blockDim.x + threadIdx.x;
    if (i < NN) g_deg[i] = 1;               // self-loop contributes 1 to in-degree
    if (i == 0) g_odd_or = 0u;
}

// Detect int32 vs int64 edge_index: view as u32; if int64 (values < 2^32,
// nonnegative), every odd word is 0. If int32 (random node ids), OR != 0.
__global__ void k_detect(const unsigned* __restrict__ ei) {
    int i = blockIdx.x * blockDim.x + threadIdx.x;   // 65536 samples
    unsigned v = ei[2 * i + 1];
    #pragma unroll
    for (int o = 16; o; o >>= 1) v |= __shfl_xor_sync(0xffffffffu, v, o);
    if ((threadIdx.x & 31) == 0 && v) atomicOr(&g_odd_or, v);
}

__global__ void k_count(const unsigned* __restrict__ ei) {
    int e = blockIdx.x * blockDim.x + threadIdx.x;
    if (e >= NE) return;
    bool is64 = (g_odd_or == 0u);
    int d = (int)(is64 ? ei[2 * ((size_t)NE + e)] : ei[(size_t)NE + e]);
    atomicAdd(&g_deg[d], 1);
}

__global__ void k_dinv() {
    int i = blockIdx.x * blockDim.x + threadIdx.x;
    if (i < NN) g_dinv[i] = rsqrtf((float)g_deg[i]);  // deg >= 1 always
}

__global__ void k_prep(const unsigned* __restrict__ ei) {
    int e = blockIdx.x * blockDim.x + threadIdx.x;
    if (e >= NE) return;
    bool is64 = (g_odd_or == 0u);
    int s = (int)(is64 ? ei[2 * (size_t)e]          : ei[e]);
    int d = (int)(is64 ? ei[2 * ((size_t)NE + e)]   : ei[(size_t)NE + e]);
    g_src[e]  = s;
    g_dst[e]  = d;
    g_norm[e] = g_dinv[s] * g_dinv[d];
}

// ---------------------------------------------------------------
// GEMM: H[M,BN] = X[M,128] @ W[128,BN].  Epilogue also seeds
// AGG[row] = H[row] * dinv[row]^2  (the self-loop message).
// LAYER==0: X = x (arg), H = g_h.   LAYER==1: X = g_h, H = g_h2.
template <int BN, int TM, int LAYER>
__global__ void k_gemm(const float* __restrict__ Xext, const float* __restrict__ W) {
    constexpr int TXN = BN / 4;        // threads along N
    constexpr int TYN = 256 / TXN;     // threads along M
    constexpr int BM  = TM * TYN;      // = 64 for both configs
    constexpr int BK  = 32;

    __shared__ float Xs[BM * 36];      // padded stride 36 (bank-conflict-free broadcast)
    __shared__ float Ws[BK * BN];

    const float* X = (LAYER == 0) ? Xext : g_h;
    float* H   = (LAYER == 0) ? g_h : g_h2;
    float* AGG = g_agg;

    int tid  = threadIdx.x;
    int tx   = tid % TXN;
    int ty   = tid / TXN;
    int row0 = blockIdx.x * BM;

    float acc[TM][4];
    #pragma unroll
    for (int i = 0; i < TM; i++) { acc[i][0]=0.f; acc[i][1]=0.f; acc[i][2]=0.f; acc[i][3]=0.f; }

    for (int kc = 0; kc < 128; kc += BK) {
        // X tile: BM x 32  (BM*8 float4s)
        #pragma unroll
        for (int f = tid; f < BM * 8; f += 256) {
            int r = f >> 3, kq = f & 7;
            float4 v = make_float4(0.f, 0.f, 0.f, 0.f);
            int grow = row0 + r;
            if (grow < NN) v = *(const float4*)(X + (size_t)grow * 128 + kc + kq * 4);
            *(float4*)(Xs + r * 36 + kq * 4) = v;
        }
        // W tile: 32 x BN  (8*BN float4s)
        #pragma unroll
        for (int f = tid; f < 8 * BN; f += 256) {
            int kk = f / (BN / 4), cq = f % (BN / 4);
            *(float4*)(Ws + kk * BN + cq * 4) =
                *(const float4*)(W + (size_t)(kc + kk) * BN + cq * 4);
        }
        __syncthreads();

        #pragma unroll
        for (int kk = 0; kk < BK; kk++) {
            float4 b4 = *(const float4*)(Ws + kk * BN + tx * 4);
            #pragma unroll
            for (int i = 0; i < TM; i++) {
                float a = Xs[(ty * TM + i) * 36 + kk];
                acc[i][0] += a * b4.x;
                acc[i][1] += a * b4.y;
                acc[i][2] += a * b4.z;
                acc[i][3] += a * b4.w;
            }
        }
        __syncthreads();
    }

    #pragma unroll
    for (int i = 0; i < TM; i++) {
        int row = row0 + ty * TM + i;
        if (row < NN) {
            float di = g_dinv[row];
            float d2 = di * di;
            float4 h4 = make_float4(acc[i][0], acc[i][1], acc[i][2], acc[i][3]);
            *(float4*)(H + (size_t)row * BN + tx * 4) = h4;
            float4 s4 = make_float4(h4.x * d2, h4.y * d2, h4.z * d2, h4.w * d2);
            *(float4*)(AGG + (size_t)row * BN + tx * 4) = s4;
        }
    }
}

// ---------------------------------------------------------------
// Scatter: AGG[dst] += H[src] * norm, one float4 lane per thread,
// vector reduction (red.global.add.v4.f32, sm_90+).
template <int D>
__global__ void k_scatter() {
    constexpr int LPE = D / 4;                       // lanes per edge (32 or 16)
    int t = blockIdx.x * blockDim.x + threadIdx.x;   // max 51.2M, fits int
    int e = t / LPE;
    if (e >= NE) return;
    int lane = t % LPE;

    const float* H = (D == DH) ? g_h : g_h2;

    int   s = g_src[e];
    int   d = g_dst[e];
    float n = g_norm[e];

    float4 v = __ldg((const float4*)(H + (size_t)s * D) + lane);
    float4 w = make_float4(v.x * n, v.y * n, v.z * n, v.w * n);
    float* dst = g_agg + (size_t)d * D + lane * 4;
    asm volatile("red.global.add.v4.f32 [%0], {%1, %2, %3, %4};"
                 :: "l"(dst), "f"(w.x), "f"(w.y), "f"(w.z), "f"(w.w)
                 : "memory");
}

// ---------------------------------------------------------------
__device__ __forceinline__ float elu1(float x) { return x > 0.f ? x : expm1f(x); }

// out = elu(AGG + bias).  D==DH writes g_h (input to layer2); D==DO writes d_out.
template <int D>
__global__ void k_act(const float* __restrict__ b, float* __restrict__ outArg) {
    int idx = blockIdx.x * blockDim.x + threadIdx.x;  // over NN*D/4 float4s
    if (idx >= NN * (D / 4)) return;
    float* o = (D == DH) ? g_h : outArg;

    int c4 = idx % (D / 4);
    float4 bv = *(const float4*)(b + c4 * 4);
    float4 a  = ((const float4*)g_agg)[idx];
    float4 r;
    r.x = elu1(a.x + bv.x);
    r.y = elu1(a.y + bv.y);
    r.z = elu1(a.z + bv.z);
    r.w = elu1(a.w + bv.w);
    ((float4*)o)[idx] = r;
}

// ---------------------------------------------------------------
extern "C" void kernel_launch(void* const* d_in, const int* in_sizes, int n_in,
                              void* d_out, int out_size) {
    const float*    x  = (const float*)d_in[0];
    const unsigned* ei = (const unsigned*)d_in[1];
    const float*    W1 = (const float*)d_in[2];
    const float*    b1 = (const float*)d_in[3];
    const float*    W2 = (const float*)d_in[4];
    const float*    b2 = (const float*)d_in[5];
    float*          out = (float*)d_out;

    k_init  <<<(NN + 255) / 256, 256>>>();
    k_detect<<<256, 256>>>(ei);
    k_count <<<(NE + 255) / 256, 256>>>(ei);
    k_dinv  <<<(NN + 255) / 256, 256>>>();
    k_prep  <<<(NE + 255) / 256, 256>>>(ei);

    // ---- layer 1: h = elu(S (x@W1) + b1) ----
    k_gemm<DH, 8, 0><<<(NN + 63) / 64, 256>>>(x, W1);
    k_scatter<DH><<<(NE * (DH / 4) + 255) / 256, 256>>>();
    k_act<DH><<<(NN * (DH / 4) + 255) / 256, 256>>>(b1, nullptr);

    // ---- layer 2: out = elu(S (h@W2) + b2) ----
    k_gemm<DO, 4, 1><<<(NN + 63) / 64, 256>>>(x /*ignored*/, W2);
    k_scatter<DO><<<(NE * (DO / 4) + 255) / 256, 256>>>();
    k_act<DO><<<(NN * (DO / 4) + 255) / 256, 256>>>(b2, out);

    (void)in_sizes; (void)n_in; (void)out_size;
}

// round 2
// speedup vs baseline: 1.0481x; 1.0481x over previous
#include <cuda_runtime.h>
#include <math.h>

#define NN 100000
#define NE 1600000
#define DH 128
#define DO 64

// ---- scratch (static device globals; no allocation allowed) ----
__device__ float g_h   [(size_t)NN * DH];   // layer1 gemm output (pre-agg)
__device__ float g_h2  [(size_t)NN * DO];   // layer2 gemm output (pre-agg)
__device__ float g_agg [(size_t)NN * DH];   // layer1 activated output (input to gemm2)
__device__ float g_dinv[NN];
__device__ int   g_ecnt[NN];                // edge-count histogram, then fill cursor
__device__ int   g_rowptr[NN + 1];
__device__ int2  g_epair[NE];               // CSR payload: {src, norm(bits)} sorted by dst
__device__ unsigned g_odd_or;               // dtype detect: 0 => edge_index is int64

// ---------------------------------------------------------------
__global__ void k_init() {
    int i = blockIdx.x * blockDim.x + threadIdx.x;
    if (i < NN) g_ecnt[i] = 0;
    if (i == 0) g_odd_or = 0u;
}

// Detect int32 vs int64 edge_index: if int64 (node ids < 2^32), every odd
// 32-bit word is 0. If int32 payload, the OR over odd words is nonzero.
__global__ void k_detect(const unsigned* __restrict__ ei) {
    int i = blockIdx.x * blockDim.x + threadIdx.x;   // 65536 samples
    unsigned v = ei[2 * i + 1];
    #pragma unroll
    for (int o = 16; o; o >>= 1) v |= __shfl_xor_sync(0xffffffffu, v, o);
    if ((threadIdx.x & 31) == 0 && v) atomicOr(&g_odd_or, v);
}

__global__ void k_count(const unsigned* __restrict__ ei) {
    int e = blockIdx.x * blockDim.x + threadIdx.x;
    if (e >= NE) return;
    bool is64 = (g_odd_or == 0u);
    int d = (int)(is64 ? ei[2 * ((size_t)NE + e)] : ei[(size_t)NE + e]);
    atomicAdd(&g_ecnt[d], 1);
}

__global__ void k_dinv() {
    int i = blockIdx.x * blockDim.x + threadIdx.x;
    if (i < NN) g_dinv[i] = rsqrtf((float)(g_ecnt[i] + 1));  // +1 self-loop
}

// Exclusive prefix-scan of g_ecnt -> g_rowptr (single block, 1024 threads).
// Also zeroes g_ecnt for reuse as the fill cursor.
__global__ void k_scan() {
    __shared__ int wsum[32];
    const int T = 1024;
    const int CH = (NN + T - 1) / T;                 // 98
    int t = threadIdx.x, lane = t & 31, w = t >> 5;
    int base = t * CH;

    int sum = 0;
    for (int i = 0; i < CH; i++) {
        int idx = base + i;
        if (idx < NN) sum += g_ecnt[idx];
    }
    // warp inclusive scan
    int v = sum;
    #pragma unroll
    for (int o = 1; o < 32; o <<= 1) {
        int u = __shfl_up_sync(0xffffffffu, v, o);
        if (lane >= o) v += u;
    }
    if (lane == 31) wsum[w] = v;
    __syncthreads();
    if (w == 0) {
        int s = wsum[lane];
        #pragma unroll
        for (int o = 1; o < 32; o <<= 1) {
            int u = __shfl_up_sync(0xffffffffu, s, o);
            if (lane >= o) s += u;
        }
        wsum[lane] = s;                              // inclusive over warps
    }
    __syncthreads();
    int off = (w > 0 ? wsum[w - 1] : 0) + v - sum;   // exclusive offset for chunk
    for (int i = 0; i < CH; i++) {
        int idx = base + i;
        if (idx < NN) {
            g_rowptr[idx] = off;
            off += g_ecnt[idx];
            g_ecnt[idx] = 0;                         // becomes fill cursor
        }
    }
    if (t == T - 1) g_rowptr[NN] = off;              // == NE
}

__global__ void k_fill(const unsigned* __restrict__ ei) {
    int e = blockIdx.x * blockDim.x + threadIdx.x;
    if (e >= NE) return;
    bool is64 = (g_odd_or == 0u);
    int s = (int)(is64 ? ei[2 * (size_t)e]        : ei[e]);
    int d = (int)(is64 ? ei[2 * ((size_t)NE + e)] : ei[(size_t)NE + e]);
    float nrm = g_dinv[s] * g_dinv[d];
    int pos = g_rowptr[d] + atomicAdd(&g_ecnt[d], 1);
    g_epair[pos] = make_int2(s, __float_as_int(nrm));
}

// ---------------------------------------------------------------
// GEMM: H[M,BN] = X[M,128] @ W[128,BN].
// LAYER==0: X = x (arg), H = g_h.   LAYER==1: X = g_agg, H = g_h2.
template <int BN, int TM, int LAYER>
__global__ void k_gemm(const float* __restrict__ Xext, const float* __restrict__ W) {
    constexpr int TXN = BN / 4;        // threads along N
    constexpr int TYN = 256 / TXN;     // threads along M
    constexpr int BM  = TM * TYN;      // = 64
    constexpr int BK  = 32;

    __shared__ float Xs[BM * 36];
    __shared__ float Ws[BK * BN];

    const float* X = (LAYER == 0) ? Xext : g_agg;
    float* H = (LAYER == 0) ? g_h : g_h2;

    int tid  = threadIdx.x;
    int tx   = tid % TXN;
    int ty   = tid / TXN;
    int row0 = blockIdx.x * BM;

    float acc[TM][4];
    #pragma unroll
    for (int i = 0; i < TM; i++) { acc[i][0]=0.f; acc[i][1]=0.f; acc[i][2]=0.f; acc[i][3]=0.f; }

    for (int kc = 0; kc < 128; kc += BK) {
        #pragma unroll
        for (int f = tid; f < BM * 8; f += 256) {
            int r = f >> 3, kq = f & 7;
            float4 v = make_float4(0.f, 0.f, 0.f, 0.f);
            int grow = row0 + r;
            if (grow < NN) v = *(const float4*)(X + (size_t)grow * 128 + kc + kq * 4);
            *(float4*)(Xs + r * 36 + kq * 4) = v;
        }
        #pragma unroll
        for (int f = tid; f < 8 * BN; f += 256) {
            int kk = f / (BN / 4), cq = f % (BN / 4);
            *(float4*)(Ws + kk * BN + cq * 4) =
                *(const float4*)(W + (size_t)(kc + kk) * BN + cq * 4);
        }
        __syncthreads();

        #pragma unroll
        for (int kk = 0; kk < BK; kk++) {
            float4 b4 = *(const float4*)(Ws + kk * BN + tx * 4);
            #pragma unroll
            for (int i = 0; i < TM; i++) {
                float a = Xs[(ty * TM + i) * 36 + kk];
                acc[i][0] += a * b4.x;
                acc[i][1] += a * b4.y;
                acc[i][2] += a * b4.z;
                acc[i][3] += a * b4.w;
            }
        }
        __syncthreads();
    }

    #pragma unroll
    for (int i = 0; i < TM; i++) {
        int row = row0 + ty * TM + i;
        if (row < NN)
            *(float4*)(H + (size_t)row * BN + tx * 4) =
                make_float4(acc[i][0], acc[i][1], acc[i][2], acc[i][3]);
    }
}

// ---------------------------------------------------------------
__device__ __forceinline__ float elu1(float x) { return x > 0.f ? x : expm1f(x); }

// CSR gather-reduce, one warp per dst node. Fuses self-loop + bias + ELU.
// D==DH: H=g_h, O=g_agg (4 floats/lane).  D==DO: H=g_h2, O=outp (2 floats/lane).
template <int D>
__global__ void k_agg(const float* __restrict__ bias, float* __restrict__ outp) {
    int node = (blockIdx.x * blockDim.x + threadIdx.x) >> 5;
    if (node >= NN) return;
    int lane = threadIdx.x & 31;
    constexpr int VL = D / 32;                        // 4 or 2

    const float* H = (D == DH) ? g_h : g_h2;
    float* O = (D == DH) ? g_agg : outp;

    float acc[VL];
    #pragma unroll
    for (int k = 0; k < VL; k++) acc[k] = 0.f;

    int beg = g_rowptr[node], end = g_rowptr[node + 1];
    for (int b = beg; b < end; b += 32) {
        int cnt = min(32, end - b);
        int2 p = make_int2(0, 0);
        if (lane < cnt) p = g_epair[b + lane];
        for (int j = 0; j < cnt; j++) {
            int   s   = __shfl_sync(0xffffffffu, p.x, j);
            float nrm = __int_as_float(__shfl_sync(0xffffffffu, p.y, j));
            if (D == DH) {
                float4 v = *(const float4*)(H + (size_t)s * D + lane * 4);
                acc[0] += v.x * nrm; acc[1] += v.y * nrm;
                acc[2] += v.z * nrm; acc[3] += v.w * nrm;
            } else {
                float2 v = *(const float2*)(H + (size_t)s * D + lane * 2);
                acc[0] += v.x * nrm; acc[1] += v.y * nrm;
            }
        }
    }

    // self-loop + bias + ELU + store
    float di = g_dinv[node], d2 = di * di;
    if (D == DH) {
        float4 hv = *(const float4*)(H + (size_t)node * D + lane * 4);
        float4 bv = *(const float4*)(bias + lane * 4);
        float4 r;
        r.x = elu1(acc[0] + hv.x * d2 + bv.x);
        r.y = elu1(acc[1] + hv.y * d2 + bv.y);
        r.z = elu1(acc[2] + hv.z * d2 + bv.z);
        r.w = elu1(acc[3] + hv.w * d2 + bv.w);
        *(float4*)(O + (size_t)node * D + lane * 4) = r;
    } else {
        float2 hv = *(const float2*)(H + (size_t)node * D + lane * 2);
        float2 bv = *(const float2*)(bias + lane * 2);
        float2 r;
        r.x = elu1(acc[0] + hv.x * d2 + bv.x);
        r.y = elu1(acc[1] + hv.y * d2 + bv.y);
        *(float2*)(O + (size_t)node * D + lane * 2) = r;
    }
}

// ---------------------------------------------------------------
extern "C" void kernel_launch(void* const* d_in, const int* in_sizes, int n_in,
                              void* d_out, int out_size) {
    const float*    x  = (const float*)d_in[0];
    const unsigned* ei = (const unsigned*)d_in[1];
    const float*    W1 = (const float*)d_in[2];
    const float*    b1 = (const float*)d_in[3];
    const float*    W2 = (const float*)d_in[4];
    const float*    b2 = (const float*)d_in[5];
    float*          out = (float*)d_out;

    // ---- CSR build ----
    k_init  <<<(NN + 255) / 256, 256>>>();
    k_detect<<<256, 256>>>(ei);
    k_count <<<(NE + 255) / 256, 256>>>(ei);
    k_dinv  <<<(NN + 255) / 256, 256>>>();
    k_scan  <<<1, 1024>>>();
    k_fill  <<<(NE + 255) / 256, 256>>>(ei);

    // ---- layer 1: g_agg = elu(S (x@W1) + b1) ----
    k_gemm<DH, 8, 0><<<(NN + 63) / 64, 256>>>(x, W1);
    k_agg<DH><<<(NN * 32 + 255) / 256, 256>>>(b1, nullptr);

    // ---- layer 2: out = elu(S (g_agg@W2) + b2) ----
    k_gemm<DO, 4, 1><<<(NN + 63) / 64, 256>>>(nullptr, W2);
    k_agg<DO><<<(NN * 32 + 255) / 256, 256>>>(b2, out);

    (void)in_sizes; (void)n_in; (void)out_size;
}

// round 3
// speedup vs baseline: 1.0757x; 1.0263x over previous
#include <cuda_runtime.h>
#include <math.h>

#define NN 100000
#define NE 1600000
#define DH 128
#define DO 64

// ---- scratch (static device globals; no allocation allowed) ----
__device__ float g_h   [(size_t)NN * DH];   // layer1 gemm output (pre-agg)
__device__ float g_h2  [(size_t)NN * DO];   // layer2 gemm output (pre-agg)
__device__ float g_agg [(size_t)NN * DH];   // layer1 activated output (input to gemm2)
__device__ float g_dinv[NN];
__device__ int   g_ecnt[NN];                // edge-count histogram, then fill cursor
__device__ int   g_rowptr[NN + 1];
__device__ int2  g_epair[NE];               // CSR payload: {src, norm(bits)} sorted by dst
__device__ unsigned g_odd_or;               // dtype detect: 0 => edge_index is int64

// ---------------------------------------------------------------
__global__ void k_init() {
    int i = blockIdx.x * blockDim.x + threadIdx.x;
    if (i < NN) g_ecnt[i] = 0;
    if (i == 0) g_odd_or = 0u;
}

__global__ void k_detect(const unsigned* __restrict__ ei) {
    int i = blockIdx.x * blockDim.x + threadIdx.x;   // 65536 samples
    unsigned v = ei[2 * i + 1];
    #pragma unroll
    for (int o = 16; o; o >>= 1) v |= __shfl_xor_sync(0xffffffffu, v, o);
    if ((threadIdx.x & 31) == 0 && v) atomicOr(&g_odd_or, v);
}

__global__ void k_count(const unsigned* __restrict__ ei) {
    int e = blockIdx.x * blockDim.x + threadIdx.x;
    if (e >= NE) return;
    bool is64 = (g_odd_or == 0u);
    int d = (int)(is64 ? ei[2 * ((size_t)NE + e)] : ei[(size_t)NE + e]);
    atomicAdd(&g_ecnt[d], 1);
}

__global__ void k_dinv() {
    int i = blockIdx.x * blockDim.x + threadIdx.x;
    if (i < NN) g_dinv[i] = rsqrtf((float)(g_ecnt[i] + 1));  // +1 self-loop
}

// Exclusive prefix-scan of g_ecnt -> g_rowptr (single block); zero cursors.
__global__ void k_scan() {
    __shared__ int wsum[32];
    const int T = 1024;
    const int CH = (NN + T - 1) / T;
    int t = threadIdx.x, lane = t & 31, w = t >> 5;
    int base = t * CH;

    int sum = 0;
    for (int i = 0; i < CH; i++) {
        int idx = base + i;
        if (idx < NN) sum += g_ecnt[idx];
    }
    int v = sum;
    #pragma unroll
    for (int o = 1; o < 32; o <<= 1) {
        int u = __shfl_up_sync(0xffffffffu, v, o);
        if (lane >= o) v += u;
    }
    if (lane == 31) wsum[w] = v;
    __syncthreads();
    if (w == 0) {
        int s = wsum[lane];
        #pragma unroll
        for (int o = 1; o < 32; o <<= 1) {
            int u = __shfl_up_sync(0xffffffffu, s, o);
            if (lane >= o) s += u;
        }
        wsum[lane] = s;
    }
    __syncthreads();
    int off = (w > 0 ? wsum[w - 1] : 0) + v - sum;
    for (int i = 0; i < CH; i++) {
        int idx = base + i;
        if (idx < NN) {
            g_rowptr[idx] = off;
            off += g_ecnt[idx];
            g_ecnt[idx] = 0;
        }
    }
    if (t == T - 1) g_rowptr[NN] = off;
}

__global__ void k_fill(const unsigned* __restrict__ ei) {
    int e = blockIdx.x * blockDim.x + threadIdx.x;
    if (e >= NE) return;
    bool is64 = (g_odd_or == 0u);
    int s = (int)(is64 ? ei[2 * (size_t)e]        : ei[e]);
    int d = (int)(is64 ? ei[2 * ((size_t)NE + e)] : ei[(size_t)NE + e]);
    float nrm = g_dinv[s] * g_dinv[d];
    int pos = g_rowptr[d] + atomicAdd(&g_ecnt[d], 1);
    g_epair[pos] = make_int2(s, __float_as_int(nrm));
}

// ---------------------------------------------------------------
// 3xTF32 tensor-core GEMM: H[M,BN] = X[M,128] @ W[128,BN], fp32-accurate.
// LAYER==0: X = x (arg), H = g_h.   LAYER==1: X = g_agg, H = g_h2.
__device__ __forceinline__ unsigned f2tf(float f) {
    unsigned u; asm("cvt.rna.tf32.f32 %0, %1;" : "=r"(u) : "f"(f)); return u;
}
__device__ __forceinline__ void mma8(float* c, const unsigned* a, const unsigned* b) {
    asm volatile("mma.sync.aligned.m16n8k8.row.col.f32.tf32.tf32.f32 "
                 "{%0,%1,%2,%3}, {%4,%5,%6,%7}, {%8,%9}, {%0,%1,%2,%3};"
                 : "+f"(c[0]), "+f"(c[1]), "+f"(c[2]), "+f"(c[3])
                 : "r"(a[0]), "r"(a[1]), "r"(a[2]), "r"(a[3]), "r"(b[0]), "r"(b[1]));
}

template <int BN, int LAYER>
__global__ __launch_bounds__(256) void k_mma(const float* __restrict__ Xext,
                                             const float* __restrict__ W) {
    constexpr int BM = 128, BK = 16;
    constexpr int NT = (BN / 2) / 8;        // n-tiles per warp (8 or 4)
    constexpr int XS = 20;                  // Xs row stride (conflict-free A frags)
    constexpr int WS = BN + 8;              // Ws row stride (8 mod 32 -> conflict-free B)

    __shared__ unsigned XsH[BM * XS], XsL[BM * XS];
    __shared__ unsigned WsH[BK * WS], WsL[BK * WS];

    const float* X = (LAYER == 0) ? Xext : g_agg;
    float* H = (LAYER == 0) ? g_h : g_h2;

    int tid = threadIdx.x;
    int lane = tid & 31, wid = tid >> 5;
    int wm = (wid & 3) * 32;                // warp m offset within block
    int wn = (wid >> 2) * (BN / 2);         // warp n offset
    int g = lane >> 2, r = lane & 3;
    int row0 = blockIdx.x * BM;

    float acc[2][NT][4];
    #pragma unroll
    for (int t = 0; t < 2; t++)
        #pragma unroll
        for (int n = 0; n < NT; n++)
            #pragma unroll
            for (int q = 0; q < 4; q++) acc[t][n][q] = 0.f;

    for (int kc = 0; kc < 128; kc += BK) {
        // X tile: BM x BK, split into tf32 hi/lo
        #pragma unroll
        for (int f = tid; f < BM * (BK / 4); f += 256) {
            int rr = f / (BK / 4), kq = f % (BK / 4);
            float4 v = make_float4(0.f, 0.f, 0.f, 0.f);
            int grow = row0 + rr;
            if (grow < NN) v = *(const float4*)(X + (size_t)grow * 128 + kc + kq * 4);
            unsigned h0 = f2tf(v.x), h1 = f2tf(v.y), h2 = f2tf(v.z), h3 = f2tf(v.w);
            unsigned l0 = f2tf(v.x - __uint_as_float(h0));
            unsigned l1 = f2tf(v.y - __uint_as_float(h1));
            unsigned l2 = f2tf(v.z - __uint_as_float(h2));
            unsigned l3 = f2tf(v.w - __uint_as_float(h3));
            *(uint4*)(XsH + rr * XS + kq * 4) = make_uint4(h0, h1, h2, h3);
            *(uint4*)(XsL + rr * XS + kq * 4) = make_uint4(l0, l1, l2, l3);
        }
        // W tile: BK x BN, split into tf32 hi/lo
        #pragma unroll
        for (int f = tid; f < BK * (BN / 4); f += 256) {
            int kk = f / (BN / 4), nq = f % (BN / 4);
            float4 v = *(const float4*)(W + (size_t)(kc + kk) * BN + nq * 4);
            unsigned h0 = f2tf(v.x), h1 = f2tf(v.y), h2 = f2tf(v.z), h3 = f2tf(v.w);
            unsigned l0 = f2tf(v.x - __uint_as_float(h0));
            unsigned l1 = f2tf(v.y - __uint_as_float(h1));
            unsigned l2 = f2tf(v.z - __uint_as_float(h2));
            unsigned l3 = f2tf(v.w - __uint_as_float(h3));
            *(uint4*)(WsH + kk * WS + nq * 4) = make_uint4(h0, h1, h2, h3);
            *(uint4*)(WsL + kk * WS + nq * 4) = make_uint4(l0, l1, l2, l3);
        }
        __syncthreads();

        #pragma unroll
        for (int kb = 0; kb < BK; kb += 8) {
            unsigned aH[2][4], aL[2][4], bH[NT][2], bL[NT][2];
            #pragma unroll
            for (int t = 0; t < 2; t++) {
                int m0 = wm + t * 16;
                aH[t][0] = XsH[(m0 + g) * XS + kb + r];
                aH[t][1] = XsH[(m0 + 8 + g) * XS + kb + r];
                aH[t][2] = XsH[(m0 + g) * XS + kb + 4 + r];
                aH[t][3] = XsH[(m0 + 8 + g) * XS + kb + 4 + r];
                aL[t][0] = XsL[(m0 + g) * XS + kb + r];
                aL[t][1] = XsL[(m0 + 8 + g) * XS + kb + r];
                aL[t][2] = XsL[(m0 + g) * XS + kb + 4 + r];
                aL[t][3] = XsL[(m0 + 8 + g) * XS + kb + 4 + r];
            }
            #pragma unroll
            for (int n = 0; n < NT; n++) {
                int nb = wn + n * 8 + g;
                bH[n][0] = WsH[(kb + r) * WS + nb];
                bH[n][1] = WsH[(kb + 4 + r) * WS + nb];
                bL[n][0] = WsL[(kb + r) * WS + nb];
                bL[n][1] = WsL[(kb + 4 + r) * WS + nb];
            }
            #pragma unroll
            for (int t = 0; t < 2; t++)
                #pragma unroll
                for (int n = 0; n < NT; n++) {
                    mma8(acc[t][n], aL[t], bH[n]);   // lo*hi
                    mma8(acc[t][n], aH[t], bL[n]);   // hi*lo
                    mma8(acc[t][n], aH[t], bH[n]);   // hi*hi (last: dominant term)
                }
        }
        __syncthreads();
    }

    #pragma unroll
    for (int t = 0; t < 2; t++) {
        int rA = row0 + wm + t * 16 + g;
        #pragma unroll
        for (int n = 0; n < NT; n++) {
            int col = wn + n * 8 + 2 * r;
            if (rA < NN)
                *(float2*)(H + (size_t)rA * BN + col) = make_float2(acc[t][n][0], acc[t][n][1]);
            if (rA + 8 < NN)
                *(float2*)(H + (size_t)(rA + 8) * BN + col) = make_float2(acc[t][n][2], acc[t][n][3]);
        }
    }
}

// ---------------------------------------------------------------
__device__ __forceinline__ float elu1(float x) { return x > 0.f ? x : expm1f(x); }

// CSR gather-reduce, one warp per dst node, MLP=4 via manual 4x unroll.
template <int D>
__global__ void k_agg(const float* __restrict__ bias, float* __restrict__ outp) {
    int node = (blockIdx.x * blockDim.x + threadIdx.x) >> 5;
    if (node >= NN) return;
    int lane = threadIdx.x & 31;
    constexpr int VL = D / 32;                        // 4 or 2

    const float* H = (D == DH) ? g_h : g_h2;
    float* O = (D == DH) ? g_agg : outp;

    float acc[VL];
    #pragma unroll
    for (int k = 0; k < VL; k++) acc[k] = 0.f;

    int beg = g_rowptr[node], end = g_rowptr[node + 1];
    for (int b = beg; b < end; b += 32) {
        int cnt = min(32, end - b);
        int2 p = make_int2(0, 0);
        if (lane < cnt) p = g_epair[b + lane];
        int j = 0;
        for (; j + 4 <= cnt; j += 4) {
            int s0 = __shfl_sync(0xffffffffu, p.x, j);
            int s1 = __shfl_sync(0xffffffffu, p.x, j + 1);
            int s2 = __shfl_sync(0xffffffffu, p.x, j + 2);
            int s3 = __shfl_sync(0xffffffffu, p.x, j + 3);
            float n0 = __int_as_float(__shfl_sync(0xffffffffu, p.y, j));
            float n1 = __int_as_float(__shfl_sync(0xffffffffu, p.y, j + 1));
            float n2 = __int_as_float(__shfl_sync(0xffffffffu, p.y, j + 2));
            float n3 = __int_as_float(__shfl_sync(0xffffffffu, p.y, j + 3));
            if (D == DH) {
                float4 v0 = __ldg((const float4*)(H + (size_t)s0 * D) + lane);
                float4 v1 = __ldg((const float4*)(H + (size_t)s1 * D) + lane);
                float4 v2 = __ldg((const float4*)(H + (size_t)s2 * D) + lane);
                float4 v3 = __ldg((const float4*)(H + (size_t)s3 * D) + lane);
                acc[0] += v0.x * n0; acc[1] += v0.y * n0; acc[2] += v0.z * n0; acc[3] += v0.w * n0;
                acc[0] += v1.x * n1; acc[1] += v1.y * n1; acc[2] += v1.z * n1; acc[3] += v1.w * n1;
                acc[0] += v2.x * n2; acc[1] += v2.y * n2; acc[2] += v2.z * n2; acc[3] += v2.w * n2;
                acc[0] += v3.x * n3; acc[1] += v3.y * n3; acc[2] += v3.z * n3; acc[3] += v3.w * n3;
            } else {
                float2 v0 = __ldg((const float2*)(H + (size_t)s0 * D) + lane);
                float2 v1 = __ldg((const float2*)(H + (size_t)s1 * D) + lane);
                float2 v2 = __ldg((const float2*)(H + (size_t)s2 * D) + lane);
                float2 v3 = __ldg((const float2*)(H + (size_t)s3 * D) + lane);
                acc[0] += v0.x * n0; acc[1] += v0.y * n0;
                acc[0] += v1.x * n1; acc[1] += v1.y * n1;
                acc[0] += v2.x * n2; acc[1] += v2.y * n2;
                acc[0] += v3.x * n3; acc[1] += v3.y * n3;
            }
        }
        for (; j < cnt; j++) {
            int   s   = __shfl_sync(0xffffffffu, p.x, j);
            float nrm = __int_as_float(__shfl_sync(0xffffffffu, p.y, j));
            if (D == DH) {
                float4 v = __ldg((const float4*)(H + (size_t)s * D) + lane);
                acc[0] += v.x * nrm; acc[1] += v.y * nrm;
                acc[2] += v.z * nrm; acc[3] += v.w * nrm;
            } else {
                float2 v = __ldg((const float2*)(H + (size_t)s * D) + lane);
                acc[0] += v.x * nrm; acc[1] += v.y * nrm;
            }
        }
    }

    float di = g_dinv[node], d2 = di * di;
    if (D == DH) {
        float4 hv = *(const float4*)(H + (size_t)node * D + lane * 4);
        float4 bv = *(const float4*)(bias + lane * 4);
        float4 rr;
        rr.x = elu1(acc[0] + hv.x * d2 + bv.x);
        rr.y = elu1(acc[1] + hv.y * d2 + bv.y);
        rr.z = elu1(acc[2] + hv.z * d2 + bv.z);
        rr.w = elu1(acc[3] + hv.w * d2 + bv.w);
        *(float4*)(O + (size_t)node * D + lane * 4) = rr;
    } else {
        float2 hv = *(const float2*)(H + (size_t)node * D + lane * 2);
        float2 bv = *(const float2*)(bias + lane * 2);
        float2 rr;
        rr.x = elu1(acc[0] + hv.x * d2 + bv.x);
        rr.y = elu1(acc[1] + hv.y * d2 + bv.y);
        *(float2*)(O + (size_t)node * D + lane * 2) = rr;
    }
}

// ---------------------------------------------------------------
extern "C" void kernel_launch(void* const* d_in, const int* in_sizes, int n_in,
                              void* d_out, int out_size) {
    const float*    x  = (const float*)d_in[0];
    const unsigned* ei = (const unsigned*)d_in[1];
    const float*    W1 = (const float*)d_in[2];
    const float*    b1 = (const float*)d_in[3];
    const float*    W2 = (const float*)d_in[4];
    const float*    b2 = (const float*)d_in[5];
    float*          out = (float*)d_out;

    // launch index 3 == k_mma<DH,0> so the ncu -s5-c1 window profiles the GEMM
    k_init  <<<(NN + 255) / 256, 256>>>();
    k_detect<<<256, 256>>>(ei);
    k_count <<<(NE + 255) / 256, 256>>>(ei);
    k_mma<DH, 0><<<(NN + 127) / 128, 256>>>(x, W1);      // layer1 GEMM (independent)
    k_dinv  <<<(NN + 255) / 256, 256>>>();
    k_scan  <<<1, 1024>>>();
    k_fill  <<<(NE + 255) / 256, 256>>>(ei);

    k_agg<DH><<<(NN * 32 + 255) / 256, 256>>>(b1, nullptr);

    k_mma<DO, 1><<<(NN + 127) / 128, 256>>>(nullptr, W2);
    k_agg<DO><<<(NN * 32 + 255) / 256, 256>>>(b2, out);

    (void)in_sizes; (void)n_in; (void)out_size;
}

// round 4
// speedup vs baseline: 1.1745x; 1.0918x over previous
#include <cuda_runtime.h>
#include <cuda_fp16.h>
#include <math.h>

#define NN 100000
#define NE 1600000
#define DH 128
#define DO 64

// ---- scratch (static device globals; no allocation allowed) ----
__device__ __half g_h16  [(size_t)NN * DH]; // layer1 gemm output (fp16, pre-agg)
__device__ __half g_h2_16[(size_t)NN * DO]; // layer2 gemm output (fp16, pre-agg)
__device__ float  g_agg  [(size_t)NN * DH]; // layer1 activated output (fp32, gemm2 input)
__device__ float  g_dinv [NN];
__device__ int    g_ecnt [NN];              // histogram, then fill cursor
__device__ int    g_rowptr[NN + 1];
__device__ int2   g_epair[NE];              // CSR payload: {src, norm(bits)} sorted by dst
__device__ unsigned g_odd_or;               // dtype detect: 0 => edge_index is int64

// ---------------------------------------------------------------
__global__ void k_init() {
    int i = blockIdx.x * blockDim.x + threadIdx.x;
    if (i < NN) g_ecnt[i] = 0;
    if (i == 0) g_odd_or = 0u;
}

__global__ void k_detect(const unsigned* __restrict__ ei) {
    int i = blockIdx.x * blockDim.x + threadIdx.x;   // 65536 samples
    unsigned v = ei[2 * i + 1];
    #pragma unroll
    for (int o = 16; o; o >>= 1) v |= __shfl_xor_sync(0xffffffffu, v, o);
    if ((threadIdx.x & 31) == 0 && v) atomicOr(&g_odd_or, v);
}

__global__ void k_count(const unsigned* __restrict__ ei) {
    int e = blockIdx.x * blockDim.x + threadIdx.x;
    if (e >= NE) return;
    bool is64 = (g_odd_or == 0u);
    int d = (int)(is64 ? ei[2 * ((size_t)NE + e)] : ei[(size_t)NE + e]);
    atomicAdd(&g_ecnt[d], 1);
}

__global__ void k_dinv() {
    int i = blockIdx.x * blockDim.x + threadIdx.x;
    if (i < NN) g_dinv[i] = rsqrtf((float)(g_ecnt[i] + 1));  // +1 self-loop
}

// Exclusive prefix-scan of g_ecnt -> g_rowptr (single block); zero cursors.
__global__ void k_scan() {
    __shared__ int wsum[32];
    const int T = 1024;
    const int CH = (NN + T - 1) / T;
    int t = threadIdx.x, lane = t & 31, w = t >> 5;
    int base = t * CH;

    int sum = 0;
    for (int i = 0; i < CH; i++) {
        int idx = base + i;
        if (idx < NN) sum += g_ecnt[idx];
    }
    int v = sum;
    #pragma unroll
    for (int o = 1; o < 32; o <<= 1) {
        int u = __shfl_up_sync(0xffffffffu, v, o);
        if (lane >= o) v += u;
    }
    if (lane == 31) wsum[w] = v;
    __syncthreads();
    if (w == 0) {
        int s = wsum[lane];
        #pragma unroll
        for (int o = 1; o < 32; o <<= 1) {
            int u = __shfl_up_sync(0xffffffffu, s, o);
            if (lane >= o) s += u;
        }
        wsum[lane] = s;
    }
    __syncthreads();
    int off = (w > 0 ? wsum[w - 1] : 0) + v - sum;
    for (int i = 0; i < CH; i++) {
        int idx = base + i;
        if (idx < NN) {
            g_rowptr[idx] = off;
            off += g_ecnt[idx];
            g_ecnt[idx] = 0;
        }
    }
    if (t == T - 1) g_rowptr[NN] = off;
}

__global__ void k_fill(const unsigned* __restrict__ ei) {
    int e = blockIdx.x * blockDim.x + threadIdx.x;
    if (e >= NE) return;
    bool is64 = (g_odd_or == 0u);
    int s = (int)(is64 ? ei[2 * (size_t)e]        : ei[e]);
    int d = (int)(is64 ? ei[2 * ((size_t)NE + e)] : ei[(size_t)NE + e]);
    float nrm = g_dinv[s] * g_dinv[d];
    int pos = g_rowptr[d] + atomicAdd(&g_ecnt[d], 1);
    g_epair[pos] = make_int2(s, __float_as_int(nrm));
}

// ---------------------------------------------------------------
// 3xTF32 tensor-core GEMM: H16[M,BN] = fp16(X[M,128] @ W[128,BN]).
// LAYER==0: X = x (arg), H = g_h16.   LAYER==1: X = g_agg, H = g_h2_16.
__device__ __forceinline__ unsigned f2tf(float f) {
    unsigned u; asm("cvt.rna.tf32.f32 %0, %1;" : "=r"(u) : "f"(f)); return u;
}
__device__ __forceinline__ void mma8(float* c, const unsigned* a, const unsigned* b) {
    asm volatile("mma.sync.aligned.m16n8k8.row.col.f32.tf32.tf32.f32 "
                 "{%0,%1,%2,%3}, {%4,%5,%6,%7}, {%8,%9}, {%0,%1,%2,%3};"
                 : "+f"(c[0]), "+f"(c[1]), "+f"(c[2]), "+f"(c[3])
                 : "r"(a[0]), "r"(a[1]), "r"(a[2]), "r"(a[3]), "r"(b[0]), "r"(b[1]));
}

template <int BN, int LAYER>
__global__ __launch_bounds__(256) void k_mma(const float* __restrict__ Xext,
                                             const float* __restrict__ W) {
    constexpr int BM = 128, BK = 16;
    constexpr int NT = (BN / 2) / 8;
    constexpr int XS = 20;
    constexpr int WS = BN + 8;

    __shared__ unsigned XsH[BM * XS], XsL[BM * XS];
    __shared__ unsigned WsH[BK * WS], WsL[BK * WS];

    const float* X = (LAYER == 0) ? Xext : g_agg;
    __half* H = (LAYER == 0) ? g_h16 : g_h2_16;

    int tid = threadIdx.x;
    int lane = tid & 31, wid = tid >> 5;
    int wm = (wid & 3) * 32;
    int wn = (wid >> 2) * (BN / 2);
    int g = lane >> 2, r = lane & 3;
    int row0 = blockIdx.x * BM;

    float acc[2][NT][4];
    #pragma unroll
    for (int t = 0; t < 2; t++)
        #pragma unroll
        for (int n = 0; n < NT; n++)
            #pragma unroll
            for (int q = 0; q < 4; q++) acc[t][n][q] = 0.f;

    for (int kc = 0; kc < 128; kc += BK) {
        #pragma unroll
        for (int f = tid; f < BM * (BK / 4); f += 256) {
            int rr = f / (BK / 4), kq = f % (BK / 4);
            float4 v = make_float4(0.f, 0.f, 0.f, 0.f);
            int grow = row0 + rr;
            if (grow < NN) v = *(const float4*)(X + (size_t)grow * 128 + kc + kq * 4);
            unsigned h0 = f2tf(v.x), h1 = f2tf(v.y), h2 = f2tf(v.z), h3 = f2tf(v.w);
            unsigned l0 = f2tf(v.x - __uint_as_float(h0));
            unsigned l1 = f2tf(v.y - __uint_as_float(h1));
            unsigned l2 = f2tf(v.z - __uint_as_float(h2));
            unsigned l3 = f2tf(v.w - __uint_as_float(h3));
            *(uint4*)(XsH + rr * XS + kq * 4) = make_uint4(h0, h1, h2, h3);
            *(uint4*)(XsL + rr * XS + kq * 4) = make_uint4(l0, l1, l2, l3);
        }
        #pragma unroll
        for (int f = tid; f < BK * (BN / 4); f += 256) {
            int kk = f / (BN / 4), nq = f % (BN / 4);
            float4 v = *(const float4*)(W + (size_t)(kc + kk) * BN + nq * 4);
            unsigned h0 = f2tf(v.x), h1 = f2tf(v.y), h2 = f2tf(v.z), h3 = f2tf(v.w);
            unsigned l0 = f2tf(v.x - __uint_as_float(h0));
            unsigned l1 = f2tf(v.y - __uint_as_float(h1));
            unsigned l2 = f2tf(v.z - __uint_as_float(h2));
            unsigned l3 = f2tf(v.w - __uint_as_float(h3));
            *(uint4*)(WsH + kk * WS + nq * 4) = make_uint4(h0, h1, h2, h3);
            *(uint4*)(WsL + kk * WS + nq * 4) = make_uint4(l0, l1, l2, l3);
        }
        __syncthreads();

        #pragma unroll
        for (int kb = 0; kb < BK; kb += 8) {
            unsigned aH[2][4], aL[2][4], bH[NT][2], bL[NT][2];
            #pragma unroll
            for (int t = 0; t < 2; t++) {
                int m0 = wm + t * 16;
                aH[t][0] = XsH[(m0 + g) * XS + kb + r];
                aH[t][1] = XsH[(m0 + 8 + g) * XS + kb + r];
                aH[t][2] = XsH[(m0 + g) * XS + kb + 4 + r];
                aH[t][3] = XsH[(m0 + 8 + g) * XS + kb + 4 + r];
                aL[t][0] = XsL[(m0 + g) * XS + kb + r];
                aL[t][1] = XsL[(m0 + 8 + g) * XS + kb + r];
                aL[t][2] = XsL[(m0 + g) * XS + kb + 4 + r];
                aL[t][3] = XsL[(m0 + 8 + g) * XS + kb + 4 + r];
            }
            #pragma unroll
            for (int n = 0; n < NT; n++) {
                int nb = wn + n * 8 + g;
                bH[n][0] = WsH[(kb + r) * WS + nb];
                bH[n][1] = WsH[(kb + 4 + r) * WS + nb];
                bL[n][0] = WsL[(kb + r) * WS + nb];
                bL[n][1] = WsL[(kb + 4 + r) * WS + nb];
            }
            #pragma unroll
            for (int t = 0; t < 2; t++)
                #pragma unroll
                for (int n = 0; n < NT; n++) {
                    mma8(acc[t][n], aL[t], bH[n]);
                    mma8(acc[t][n], aH[t], bL[n]);
                    mma8(acc[t][n], aH[t], bH[n]);
                }
        }
        __syncthreads();
    }

    #pragma unroll
    for (int t = 0; t < 2; t++) {
        int rA = row0 + wm + t * 16 + g;
        #pragma unroll
        for (int n = 0; n < NT; n++) {
            int col = wn + n * 8 + 2 * r;
            if (rA < NN)
                *(__half2*)(H + (size_t)rA * BN + col) =
                    __floats2half2_rn(acc[t][n][0], acc[t][n][1]);
            if (rA + 8 < NN)
                *(__half2*)(H + (size_t)(rA + 8) * BN + col) =
                    __floats2half2_rn(acc[t][n][2], acc[t][n][3]);
        }
    }
}

// ---------------------------------------------------------------
__device__ __forceinline__ float elu1(float x) { return x > 0.f ? x : expm1f(x); }

__device__ __forceinline__ void acc128(float* acc, uint2 u, float n) {
    __half2 h0 = *reinterpret_cast<__half2*>(&u.x);
    __half2 h1 = *reinterpret_cast<__half2*>(&u.y);
    float2 f0 = __half22float2(h0), f1 = __half22float2(h1);
    acc[0] += f0.x * n; acc[1] += f0.y * n;
    acc[2] += f1.x * n; acc[3] += f1.y * n;
}
__device__ __forceinline__ void acc64(float* acc, unsigned u, float n) {
    float2 f0 = __half22float2(*reinterpret_cast<__half2*>(&u));
    acc[0] += f0.x * n; acc[1] += f0.y * n;
}

// CSR gather-reduce, one warp per dst node. fp16 rows, fp32 accumulation.
// Edge metadata read by uniform warp-broadcast __ldg (L1-hit heavy).
template <int D>
__global__ void k_agg(const float* __restrict__ bias, float* __restrict__ outp) {
    int node = (blockIdx.x * blockDim.x + threadIdx.x) >> 5;
    if (node >= NN) return;
    int lane = threadIdx.x & 31;
    constexpr int VL = D / 32;

    const __half* H = (D == DH) ? g_h16 : g_h2_16;
    float* O = (D == DH) ? g_agg : outp;

    float acc[VL];
    #pragma unroll
    for (int k = 0; k < VL; k++) acc[k] = 0.f;

    int beg = g_rowptr[node], end = g_rowptr[node + 1];
    int j = beg;
    for (; j + 8 <= end; j += 8) {
        int2 p[8];
        #pragma unroll
        for (int i = 0; i < 8; i++) p[i] = __ldg(&g_epair[j + i]);
        if (D == DH) {
            uint2 u[8];
            #pragma unroll
            for (int i = 0; i < 8; i++)
                u[i] = __ldg((const uint2*)(H + (size_t)p[i].x * D) + lane);
            #pragma unroll
            for (int i = 0; i < 8; i++)
                acc128(acc, u[i], __int_as_float(p[i].y));
        } else {
            unsigned u[8];
            #pragma unroll
            for (int i = 0; i < 8; i++)
                u[i] = __ldg((const unsigned*)(H + (size_t)p[i].x * D) + lane);
            #pragma unroll
            for (int i = 0; i < 8; i++)
                acc64(acc, u[i], __int_as_float(p[i].y));
        }
    }
    for (; j < end; j++) {
        int2 p = __ldg(&g_epair[j]);
        float n = __int_as_float(p.y);
        if (D == DH) {
            uint2 u = __ldg((const uint2*)(H + (size_t)p.x * D) + lane);
            acc128(acc, u, n);
        } else {
            unsigned u = __ldg((const unsigned*)(H + (size_t)p.x * D) + lane);
            acc64(acc, u, n);
        }
    }

    // self-loop + bias + ELU + store (fp32 output)
    float di = g_dinv[node], d2 = di * di;
    if (D == DH) {
        uint2 us = __ldg((const uint2*)(H + (size_t)node * D) + lane);
        float hv[4] = {0.f, 0.f, 0.f, 0.f};
        acc128(hv, us, d2);
        float4 bv = *(const float4*)(bias + lane * 4);
        float4 rr;
        rr.x = elu1(acc[0] + hv[0] + bv.x);
        rr.y = elu1(acc[1] + hv[1] + bv.y);
        rr.z = elu1(acc[2] + hv[2] + bv.z);
        rr.w = elu1(acc[3] + hv[3] + bv.w);
        *(float4*)(O + (size_t)node * D + lane * 4) = rr;
    } else {
        unsigned us = __ldg((const unsigned*)(H + (size_t)node * D) + lane);
        float hv[2] = {0.f, 0.f};
        acc64(hv, us, d2);
        float2 bv = *(const float2*)(bias + lane * 2);
        float2 rr;
        rr.x = elu1(acc[0] + hv[0] + bv.x);
        rr.y = elu1(acc[1] + hv[1] + bv.y);
        *(float2*)(O + (size_t)node * D + lane * 2) = rr;
    }
}

// ---------------------------------------------------------------
extern "C" void kernel_launch(void* const* d_in, const int* in_sizes, int n_in,
                              void* d_out, int out_size) {
    const float*    x  = (const float*)d_in[0];
    const unsigned* ei = (const unsigned*)d_in[1];
    const float*    W1 = (const float*)d_in[2];
    const float*    b1 = (const float*)d_in[3];
    const float*    W2 = (const float*)d_in[4];
    const float*    b2 = (const float*)d_in[5];
    float*          out = (float*)d_out;

    // launch index 3 == k_mma<DH,0> (the ncu -s5-c1 window lands on index 3)
    k_init  <<<(NN + 255) / 256, 256>>>();
    k_detect<<<256, 256>>>(ei);
    k_count <<<(NE + 255) / 256, 256>>>(ei);
    k_mma<DH, 0><<<(NN + 127) / 128, 256>>>(x, W1);
    k_dinv  <<<(NN + 255) / 256, 256>>>();
    k_scan  <<<1, 1024>>>();
    k_fill  <<<(NE + 255) / 256, 256>>>(ei);

    k_agg<DH><<<(NN * 32 + 255) / 256, 256>>>(b1, nullptr);

    k_mma<DO, 1><<<(NN + 127) / 128, 256>>>(nullptr, W2);
    k_agg<DO><<<(NN * 32 + 255) / 256, 256>>>(b2, out);

    (void)in_sizes; (void)n_in; (void)out_size;
}

// round 5
// speedup vs baseline: 1.9049x; 1.6219x over previous
#include <cuda_runtime.h>
#include <cuda_fp16.h>
#include <math.h>

#define NN 100000
#define NE 1600000
#define DH 128
#define DO 64
#define NB 98   // ceil(NN/1024)

// ---- scratch (static device globals; no allocation allowed) ----
__device__ __half g_h16  [(size_t)NN * DH]; // layer1 gemm output (fp16, pre-agg)
__device__ __half g_h2_16[(size_t)NN * DO]; // layer2 gemm output (fp16, pre-agg)
__device__ __half g_agg16[(size_t)NN * DH]; // layer1 activated output (fp16, gemm2 input)
__device__ float  g_dinv [NN];
__device__ int    g_ecnt [NN];              // histogram, then fill cursor
__device__ int    g_rowptr[NN + 1];
__device__ int    g_bsum[NB];
__device__ int    g_boff[NB];
__device__ int2   g_epair[NE];              // CSR payload: {src, norm(bits)} sorted by dst
__device__ unsigned g_odd_or;               // 0 => edge_index is int64 (idempotent OR)

// ---------------------------------------------------------------
// init cursors + dtype detect (odd 32-bit words all zero <=> int64)
__global__ void k_init(const unsigned* __restrict__ ei) {
    int i = blockIdx.x * blockDim.x + threadIdx.x;
    if (i < NN) g_ecnt[i] = 0;
    if (i < 65536) {
        unsigned v = ei[2 * i + 1];
        #pragma unroll
        for (int o = 16; o; o >>= 1) v |= __shfl_xor_sync(0xffffffffu, v, o);
        if ((threadIdx.x & 31) == 0 && v) atomicOr(&g_odd_or, v);
    }
}

__global__ void k_count(const unsigned* __restrict__ ei) {
    int e = blockIdx.x * blockDim.x + threadIdx.x;
    if (e >= NE) return;
    bool is64 = (g_odd_or == 0u);
    int d = (int)(is64 ? ei[2 * ((size_t)NE + e)] : ei[(size_t)NE + e]);
    atomicAdd(&g_ecnt[d], 1);
}

// P1: per-block sum of g_ecnt (coalesced) + fused dinv.
__global__ __launch_bounds__(1024) void k_p1() {
    __shared__ int ws[32];
    int t = threadIdx.x, idx = blockIdx.x * 1024 + t;
    int v = (idx < NN) ? g_ecnt[idx] : 0;
    if (idx < NN) g_dinv[idx] = rsqrtf((float)(v + 1));
    int s = v;
    #pragma unroll
    for (int o = 16; o; o >>= 1) s += __shfl_xor_sync(0xffffffffu, s, o);
    if ((t & 31) == 0) ws[t >> 5] = s;
    __syncthreads();
    if (t < 32) {
        int x = ws[t];
        #pragma unroll
        for (int o = 16; o; o >>= 1) x += __shfl_xor_sync(0xffffffffu, x, o);
        if (t == 0) g_bsum[blockIdx.x] = x;
    }
}

// P2: exclusive scan of 98 block sums (1 block, 128 threads).
__global__ void k_p2() {
    __shared__ int ws[4];
    int t = threadIdx.x, lane = t & 31, w = t >> 5;
    int v = (t < NB) ? g_bsum[t] : 0;
    int p = v;
    #pragma unroll
    for (int o = 1; o < 32; o <<= 1) {
        int u = __shfl_up_sync(0xffffffffu, p, o);
        if (lane >= o) p += u;
    }
    if (lane == 31) ws[w] = p;
    __syncthreads();
    int woff = 0;
    #pragma unroll
    for (int k = 0; k < 4; k++) if (k < w) woff += ws[k];
    int incl = p + woff;
    if (t < NB) g_boff[t] = incl - v;
    if (t == NB - 1) g_rowptr[NN] = incl;
}

// P3: coalesced block-scan -> rowptr; zero cursors.
__global__ __launch_bounds__(1024) void k_p3() {
    __shared__ int ws[32];
    int t = threadIdx.x, lane = t & 31, w = t >> 5;
    int idx = blockIdx.x * 1024 + t;
    int v = (idx < NN) ? g_ecnt[idx] : 0;
    int p = v;
    #pragma unroll
    for (int o = 1; o < 32; o <<= 1) {
        int u = __shfl_up_sync(0xffffffffu, p, o);
        if (lane >= o) p += u;
    }
    if (lane == 31) ws[w] = p;
    __syncthreads();
    if (t < 32) {
        int x = ws[t];
        #pragma unroll
        for (int o = 1; o < 32; o <<= 1) {
            int u = __shfl_up_sync(0xffffffffu, x, o);
            if (lane >= o) x += u;
        }
        ws[t] = x - ws[t];                      // exclusive warp offsets
    }
    __syncthreads();
    if (idx < NN) {
        g_rowptr[idx] = g_boff[blockIdx.x] + ws[w] + p - v;
        g_ecnt[idx] = 0;
    }
}

__global__ void k_fill(const unsigned* __restrict__ ei) {
    int e = blockIdx.x * blockDim.x + threadIdx.x;
    if (e >= NE) return;
    bool is64 = (g_odd_or == 0u);
    int s = (int)(is64 ? ei[2 * (size_t)e]        : ei[e]);
    int d = (int)(is64 ? ei[2 * ((size_t)NE + e)] : ei[(size_t)NE + e]);
    float nrm = g_dinv[s] * g_dinv[d];
    int pos = g_rowptr[d] + atomicAdd(&g_ecnt[d], 1);
    g_epair[pos] = make_int2(s, __float_as_int(nrm));
}

// ---------------------------------------------------------------
// 3xTF32 tensor-core GEMM: H16[M,BN] = fp16(X[M,128] @ W[128,BN]).
// LAYER==0: X = x (fp32 arg), H = g_h16.  LAYER==1: X = g_agg16 (fp16), H = g_h2_16.
__device__ __forceinline__ unsigned f2tf(float f) {
    unsigned u; asm("cvt.rna.tf32.f32 %0, %1;" : "=r"(u) : "f"(f)); return u;
}
__device__ __forceinline__ void mma8(float* c, const unsigned* a, const unsigned* b) {
    asm volatile("mma.sync.aligned.m16n8k8.row.col.f32.tf32.tf32.f32 "
                 "{%0,%1,%2,%3}, {%4,%5,%6,%7}, {%8,%9}, {%0,%1,%2,%3};"
                 : "+f"(c[0]), "+f"(c[1]), "+f"(c[2]), "+f"(c[3])
                 : "r"(a[0]), "r"(a[1]), "r"(a[2]), "r"(a[3]), "r"(b[0]), "r"(b[1]));
}

template <int BN, int LAYER>
__global__ __launch_bounds__(256) void k_mma(const float* __restrict__ Xext,
                                             const float* __restrict__ W) {
    constexpr int BM = 128, BK = 16;
    constexpr int NT = (BN / 2) / 8;
    constexpr int XS = 20;
    constexpr int WS = BN + 8;

    __shared__ unsigned XsH[BM * XS], XsL[BM * XS];
    __shared__ unsigned WsH[BK * WS], WsL[BK * WS];

    __half* H = (LAYER == 0) ? g_h16 : g_h2_16;

    int tid = threadIdx.x;
    int lane = tid & 31, wid = tid >> 5;
    int wm = (wid & 3) * 32;
    int wn = (wid >> 2) * (BN / 2);
    int g = lane >> 2, r = lane & 3;
    int row0 = blockIdx.x * BM;

    float acc[2][NT][4];
    #pragma unroll
    for (int t = 0; t < 2; t++)
        #pragma unroll
        for (int n = 0; n < NT; n++)
            #pragma unroll
            for (int q = 0; q < 4; q++) acc[t][n][q] = 0.f;

    for (int kc = 0; kc < 128; kc += BK) {
        #pragma unroll
        for (int f = tid; f < BM * (BK / 4); f += 256) {
            int rr = f / (BK / 4), kq = f % (BK / 4);
            float4 v = make_float4(0.f, 0.f, 0.f, 0.f);
            int grow = row0 + rr;
            if (grow < NN) {
                if (LAYER == 0) {
                    v = *(const float4*)(Xext + (size_t)grow * 128 + kc + kq * 4);
                } else {
                    uint2 u = *(const uint2*)(g_agg16 + (size_t)grow * 128 + kc + kq * 4);
                    float2 a0 = __half22float2(*reinterpret_cast<__half2*>(&u.x));
                    float2 a1 = __half22float2(*reinterpret_cast<__half2*>(&u.y));
                    v = make_float4(a0.x, a0.y, a1.x, a1.y);
                }
            }
            unsigned h0 = f2tf(v.x), h1 = f2tf(v.y), h2 = f2tf(v.z), h3 = f2tf(v.w);
            unsigned l0 = f2tf(v.x - __uint_as_float(h0));
            unsigned l1 = f2tf(v.y - __uint_as_float(h1));
            unsigned l2 = f2tf(v.z - __uint_as_float(h2));
            unsigned l3 = f2tf(v.w - __uint_as_float(h3));
            *(uint4*)(XsH + rr * XS + kq * 4) = make_uint4(h0, h1, h2, h3);
            *(uint4*)(XsL + rr * XS + kq * 4) = make_uint4(l0, l1, l2, l3);
        }
        #pragma unroll
        for (int f = tid; f < BK * (BN / 4); f += 256) {
            int kk = f / (BN / 4), nq = f % (BN / 4);
            float4 v = *(const float4*)(W + (size_t)(kc + kk) * BN + nq * 4);
            unsigned h0 = f2tf(v.x), h1 = f2tf(v.y), h2 = f2tf(v.z), h3 = f2tf(v.w);
            unsigned l0 = f2tf(v.x - __uint_as_float(h0));
            unsigned l1 = f2tf(v.y - __uint_as_float(h1));
            unsigned l2 = f2tf(v.z - __uint_as_float(h2));
            unsigned l3 = f2tf(v.w - __uint_as_float(h3));
            *(uint4*)(WsH + kk * WS + nq * 4) = make_uint4(h0, h1, h2, h3);
            *(uint4*)(WsL + kk * WS + nq * 4) = make_uint4(l0, l1, l2, l3);
        }
        __syncthreads();

        #pragma unroll
        for (int kb = 0; kb < BK; kb += 8) {
            unsigned aH[2][4], aL[2][4], bH[NT][2], bL[NT][2];
            #pragma unroll
            for (int t = 0; t < 2; t++) {
                int m0 = wm + t * 16;
                aH[t][0] = XsH[(m0 + g) * XS + kb + r];
                aH[t][1] = XsH[(m0 + 8 + g) * XS + kb + r];
                aH[t][2] = XsH[(m0 + g) * XS + kb + 4 + r];
                aH[t][3] = XsH[(m0 + 8 + g) * XS + kb + 4 + r];
                aL[t][0] = XsL[(m0 + g) * XS + kb + r];
                aL[t][1] = XsL[(m0 + 8 + g) * XS + kb + r];
                aL[t][2] = XsL[(m0 + g) * XS + kb + 4 + r];
                aL[t][3] = XsL[(m0 + 8 + g) * XS + kb + 4 + r];
            }
            #pragma unroll
            for (int n = 0; n < NT; n++) {
                int nb = wn + n * 8 + g;
                bH[n][0] = WsH[(kb + r) * WS + nb];
                bH[n][1] = WsH[(kb + 4 + r) * WS + nb];
                bL[n][0] = WsL[(kb + r) * WS + nb];
                bL[n][1] = WsL[(kb + 4 + r) * WS + nb];
            }
            #pragma unroll
            for (int t = 0; t < 2; t++)
                #pragma unroll
                for (int n = 0; n < NT; n++) {
                    mma8(acc[t][n], aL[t], bH[n]);
                    mma8(acc[t][n], aH[t], bL[n]);
                    mma8(acc[t][n], aH[t], bH[n]);
                }
        }
        __syncthreads();
    }

    #pragma unroll
    for (int t = 0; t < 2; t++) {
        int rA = row0 + wm + t * 16 + g;
        #pragma unroll
        for (int n = 0; n < NT; n++) {
            int col = wn + n * 8 + 2 * r;
            if (rA < NN)
                *(__half2*)(H + (size_t)rA * BN + col) =
                    __floats2half2_rn(acc[t][n][0], acc[t][n][1]);
            if (rA + 8 < NN)
                *(__half2*)(H + (size_t)(rA + 8) * BN + col) =
                    __floats2half2_rn(acc[t][n][2], acc[t][n][3]);
        }
    }
}

// ---------------------------------------------------------------
__device__ __forceinline__ float elu1(float x) { return x > 0.f ? x : expm1f(x); }

__device__ __forceinline__ void acc128(float* acc, uint2 u, float n) {
    float2 f0 = __half22float2(*reinterpret_cast<__half2*>(&u.x));
    float2 f1 = __half22float2(*reinterpret_cast<__half2*>(&u.y));
    acc[0] += f0.x * n; acc[1] += f0.y * n;
    acc[2] += f1.x * n; acc[3] += f1.y * n;
}
__device__ __forceinline__ void acc64(float* acc, unsigned u, float n) {
    float2 f0 = __half22float2(*reinterpret_cast<__half2*>(&u));
    acc[0] += f0.x * n; acc[1] += f0.y * n;
}

// CSR gather-reduce, one warp per dst node. fp16 rows, fp32 accumulation.
// D==DH: out -> g_agg16 (fp16). D==DO: out -> fp32 d_out.
template <int D>
__global__ void k_agg(const float* __restrict__ bias, float* __restrict__ outp) {
    int node = (blockIdx.x * blockDim.x + threadIdx.x) >> 5;
    if (node >= NN) return;
    int lane = threadIdx.x & 31;
    constexpr int VL = D / 32;

    const __half* H = (D == DH) ? g_h16 : g_h2_16;

    float acc[VL];
    #pragma unroll
    for (int k = 0; k < VL; k++) acc[k] = 0.f;

    int beg = g_rowptr[node], end = g_rowptr[node + 1];
    int j = beg;
    for (; j + 8 <= end; j += 8) {
        int2 p[8];
        #pragma unroll
        for (int i = 0; i < 8; i++) p[i] = __ldg(&g_epair[j + i]);
        if (D == DH) {
            uint2 u[8];
            #pragma unroll
            for (int i = 0; i < 8; i++)
                u[i] = __ldg((const uint2*)(H + (size_t)p[i].x * D) + lane);
            #pragma unroll
            for (int i = 0; i < 8; i++)
                acc128(acc, u[i], __int_as_float(p[i].y));
        } else {
            unsigned u[8];
            #pragma unroll
            for (int i = 0; i < 8; i++)
                u[i] = __ldg((const unsigned*)(H + (size_t)p[i].x * D) + lane);
            #pragma unroll
            for (int i = 0; i < 8; i++)
                acc64(acc, u[i], __int_as_float(p[i].y));
        }
    }
    for (; j < end; j++) {
        int2 p = __ldg(&g_epair[j]);
        float n = __int_as_float(p.y);
        if (D == DH) {
            uint2 u = __ldg((const uint2*)(H + (size_t)p.x * D) + lane);
            acc128(acc, u, n);
        } else {
            unsigned u = __ldg((const unsigned*)(H + (size_t)p.x * D) + lane);
            acc64(acc, u, n);
        }
    }

    float di = g_dinv[node], d2 = di * di;
    if (D == DH) {
        uint2 us = __ldg((const uint2*)(H + (size_t)node * D) + lane);
        float hv[4] = {0.f, 0.f, 0.f, 0.f};
        acc128(hv, us, d2);
        float4 bv = *(const float4*)(bias + lane * 4);
        float r0 = elu1(acc[0] + hv[0] + bv.x);
        float r1 = elu1(acc[1] + hv[1] + bv.y);
        float r2 = elu1(acc[2] + hv[2] + bv.z);
        float r3 = elu1(acc[3] + hv[3] + bv.w);
        __half2 o0 = __floats2half2_rn(r0, r1);
        __half2 o1 = __floats2half2_rn(r2, r3);
        uint2 ou = make_uint2(*reinterpret_cast<unsigned*>(&o0),
                              *reinterpret_cast<unsigned*>(&o1));
        *((uint2*)(g_agg16 + (size_t)node * D) + lane) = ou;
    } else {
        unsigned us = __ldg((const unsigned*)(H + (size_t)node * D) + lane);
        float hv[2] = {0.f, 0.f};
        acc64(hv, us, d2);
        float2 bv = *(const float2*)(bias + lane * 2);
        float2 rr;
        rr.x = elu1(acc[0] + hv[0] + bv.x);
        rr.y = elu1(acc[1] + hv[1] + bv.y);
        *(float2*)(outp + (size_t)node * D + lane * 2) = rr;
    }
}

// ---------------------------------------------------------------
extern "C" void kernel_launch(void* const* d_in, const int* in_sizes, int n_in,
                              void* d_out, int out_size) {
    const float*    x  = (const float*)d_in[0];
    const unsigned* ei = (const unsigned*)d_in[1];
    const float*    W1 = (const float*)d_in[2];
    const float*    b1 = (const float*)d_in[3];
    const float*    W2 = (const float*)d_in[4];
    const float*    b2 = (const float*)d_in[5];
    float*          out = (float*)d_out;

    k_init <<<(NN + 255) / 256, 256>>>(ei);          // 0: cursors + dtype detect
    k_count<<<(NE + 255) / 256, 256>>>(ei);          // 1
    k_p1   <<<NB, 1024>>>();                         // 2: block sums + dinv
    k_mma<DH, 0><<<(NN + 127) / 128, 256>>>(x, W1);  // 3: layer1 GEMM (profiled slot)
    k_p2   <<<1, 128>>>();                           // 4
    k_p3   <<<NB, 1024>>>();                         // 5
    k_fill <<<(NE + 255) / 256, 256>>>(ei);          // 6

    k_agg<DH><<<(NN * 32 + 255) / 256, 256>>>(b1, nullptr);       // 7
    k_mma<DO, 1><<<(NN + 127) / 128, 256>>>(nullptr, W2);         // 8
    k_agg<DO><<<(NN * 32 + 255) / 256, 256>>>(b2, out);           // 9

    (void)in_sizes; (void)n_in; (void)out_size;
}

// round 6
// speedup vs baseline: 2.3071x; 1.2111x over previous
#include <cuda_runtime.h>
#include <cuda_fp16.h>
#include <math.h>

#define NN 100000
#define NE 1600000
#define DH 128
#define DO 64
#define NB 98   // ceil(NN/1024)

// ---- scratch (static device globals; no allocation allowed) ----
__device__ __half g_h16  [(size_t)NN * DH]; // layer1 gemm output (fp16)
__device__ __half g_h2_16[(size_t)NN * DO]; // layer2 gemm output (fp16)
__device__ __half g_agg16[(size_t)NN * DH]; // layer1 activated output (fp16)
__device__ __half g_w1h[DH * DH], g_w1l[DH * DH];
__device__ __half g_w2h[DH * DO], g_w2l[DH * DO];
__device__ float  g_dinv [NN];
__device__ int    g_ecnt [NN];
__device__ int    g_rowptr[NN + 1];
__device__ int    g_bsum[NB];
__device__ int    g_boff[NB];
__device__ int2   g_epair[NE];
__device__ unsigned g_odd_or;               // 0 => edge_index is int64

// ---------------------------------------------------------------
__global__ void k_init(const unsigned* __restrict__ ei) {
    int i = blockIdx.x * blockDim.x + threadIdx.x;
    if (i < NN) g_ecnt[i] = 0;
    if (i < 65536) {
        unsigned v = ei[2 * i + 1];
        #pragma unroll
        for (int o = 16; o; o >>= 1) v |= __shfl_xor_sync(0xffffffffu, v, o);
        if ((threadIdx.x & 31) == 0 && v) atomicOr(&g_odd_or, v);
    }
}

__global__ void k_count(const unsigned* __restrict__ ei) {
    int e = blockIdx.x * blockDim.x + threadIdx.x;
    if (e >= NE) return;
    bool is64 = (g_odd_or == 0u);
    int d = (int)(is64 ? ei[2 * ((size_t)NE + e)] : ei[(size_t)NE + e]);
    atomicAdd(&g_ecnt[d], 1);
}

// W hi/lo fp16 splits (once).
__global__ void k_wsplit(const float* __restrict__ W1, const float* __restrict__ W2) {
    int i = blockIdx.x * blockDim.x + threadIdx.x;
    if (i < DH * DH) {
        float v = W1[i];
        __half h = __float2half_rn(v);
        g_w1h[i] = h;
        g_w1l[i] = __float2half_rn(v - __half2float(h));
    }
    if (i < DH * DO) {
        float v = W2[i];
        __half h = __float2half_rn(v);
        g_w2h[i] = h;
        g_w2l[i] = __float2half_rn(v - __half2float(h));
    }
}

__global__ __launch_bounds__(1024) void k_p1() {
    __shared__ int ws[32];
    int t = threadIdx.x, idx = blockIdx.x * 1024 + t;
    int v = (idx < NN) ? g_ecnt[idx] : 0;
    if (idx < NN) g_dinv[idx] = rsqrtf((float)(v + 1));
    int s = v;
    #pragma unroll
    for (int o = 16; o; o >>= 1) s += __shfl_xor_sync(0xffffffffu, s, o);
    if ((t & 31) == 0) ws[t >> 5] = s;
    __syncthreads();
    if (t < 32) {
        int x = ws[t];
        #pragma unroll
        for (int o = 16; o; o >>= 1) x += __shfl_xor_sync(0xffffffffu, x, o);
        if (t == 0) g_bsum[blockIdx.x] = x;
    }
}

__global__ void k_p2() {
    __shared__ int ws[4];
    int t = threadIdx.x, lane = t & 31, w = t >> 5;
    int v = (t < NB) ? g_bsum[t] : 0;
    int p = v;
    #pragma unroll
    for (int o = 1; o < 32; o <<= 1) {
        int u = __shfl_up_sync(0xffffffffu, p, o);
        if (lane >= o) p += u;
    }
    if (lane == 31) ws[w] = p;
    __syncthreads();
    int woff = 0;
    #pragma unroll
    for (int k = 0; k < 4; k++) if (k < w) woff += ws[k];
    int incl = p + woff;
    if (t < NB) g_boff[t] = incl - v;
    if (t == NB - 1) g_rowptr[NN] = incl;
}

__global__ __launch_bounds__(1024) void k_p3() {
    __shared__ int ws[32];
    int t = threadIdx.x, lane = t & 31, w = t >> 5;
    int idx = blockIdx.x * 1024 + t;
    int v = (idx < NN) ? g_ecnt[idx] : 0;
    int p = v;
    #pragma unroll
    for (int o = 1; o < 32; o <<= 1) {
        int u = __shfl_up_sync(0xffffffffu, p, o);
        if (lane >= o) p += u;
    }
    if (lane == 31) ws[w] = p;
    __syncthreads();
    if (t < 32) {
        int x = ws[t];
        #pragma unroll
        for (int o = 1; o < 32; o <<= 1) {
            int u = __shfl_up_sync(0xffffffffu, x, o);
            if (lane >= o) x += u;
        }
        ws[t] = x - ws[t];
    }
    __syncthreads();
    if (idx < NN) {
        g_rowptr[idx] = g_boff[blockIdx.x] + ws[w] + p - v;
        g_ecnt[idx] = 0;
    }
}

__global__ void k_fill(const unsigned* __restrict__ ei) {
    int e = blockIdx.x * blockDim.x + threadIdx.x;
    if (e >= NE) return;
    bool is64 = (g_odd_or == 0u);
    int s = (int)(is64 ? ei[2 * (size_t)e]        : ei[e]);
    int d = (int)(is64 ? ei[2 * ((size_t)NE + e)] : ei[(size_t)NE + e]);
    float nrm = g_dinv[s] * g_dinv[d];
    int pos = g_rowptr[d] + atomicAdd(&g_ecnt[d], 1);
    g_epair[pos] = make_int2(s, __float_as_int(nrm));
}

// ---------------------------------------------------------------
// Split-fp16 tensor-core GEMM (m16n8k16, fp32 accum).
// LAYER==0: X = x (fp32, split hi/lo), W = g_w1{h,l}; 3 mmas/tile.  H = g_h16.
// LAYER==1: X = g_agg16 (exact fp16),  W = g_w2{h,l}; 2 mmas/tile.  H = g_h2_16.
__device__ __forceinline__ void mma16(float* c, const unsigned* a, const unsigned* b) {
    asm volatile("mma.sync.aligned.m16n8k16.row.col.f32.f16.f16.f32 "
                 "{%0,%1,%2,%3}, {%4,%5,%6,%7}, {%8,%9}, {%0,%1,%2,%3};"
                 : "+f"(c[0]), "+f"(c[1]), "+f"(c[2]), "+f"(c[3])
                 : "r"(a[0]), "r"(a[1]), "r"(a[2]), "r"(a[3]), "r"(b[0]), "r"(b[1]));
}
__device__ __forceinline__ void ldsm_x4(unsigned* r, unsigned addr) {
    asm volatile("ldmatrix.sync.aligned.m8n8.x4.shared.b16 {%0,%1,%2,%3}, [%4];"
                 : "=r"(r[0]), "=r"(r[1]), "=r"(r[2]), "=r"(r[3]) : "r"(addr));
}
__device__ __forceinline__ void ldsm_x4t(unsigned* r, unsigned addr) {
    asm volatile("ldmatrix.sync.aligned.m8n8.x4.trans.shared.b16 {%0,%1,%2,%3}, [%4];"
                 : "=r"(r[0]), "=r"(r[1]), "=r"(r[2]), "=r"(r[3]) : "r"(addr));
}

template <int BN, int LAYER>
__global__ __launch_bounds__(256) void k_mma(const float* __restrict__ Xext) {
    constexpr int BM = 128, BK = 32;
    constexpr int XS = 40;            // X smem stride (halves): conflict-free ldmatrix
    constexpr int WS = BN + 8;        // W smem stride (halves): conflict-free ldmatrix
    constexpr int NT = BN / 16;       // 8x8 n-tiles per warp (8 or 4)

    __shared__ alignas(16) __half XsH[BM * XS];
    __shared__ alignas(16) __half XsL[LAYER == 0 ? BM * XS : 8];
    __shared__ alignas(16) __half WsH[BK * WS];
    __shared__ alignas(16) __half WsL[BK * WS];

    const __half* Wh = (LAYER == 0) ? g_w1h : g_w2h;
    const __half* Wl = (LAYER == 0) ? g_w1l : g_w2l;
    __half* H = (LAYER == 0) ? g_h16 : g_h2_16;

    int tid = threadIdx.x;
    int lane = tid & 31, wid = tid >> 5;
    int wm = (wid & 3) * 32;          // warp m offset (4 m-warps)
    int wn = (wid >> 2) * (BN / 2);   // warp n offset (2 n-warps)
    int row0 = blockIdx.x * BM;

    unsigned xh_base = (unsigned)__cvta_generic_to_shared(XsH);
    unsigned xl_base = (unsigned)__cvta_generic_to_shared(XsL);
    unsigned wh_base = (unsigned)__cvta_generic_to_shared(WsH);
    unsigned wl_base = (unsigned)__cvta_generic_to_shared(WsL);

    float acc[2][NT][4];
    #pragma unroll
    for (int mt = 0; mt < 2; mt++)
        #pragma unroll
        for (int nt = 0; nt < NT; nt++)
            #pragma unroll
            for (int q = 0; q < 4; q++) acc[mt][nt][q] = 0.f;

    // ldmatrix lane addressing (halves offsets)
    int a_row = lane & 15, a_col = (lane >> 4) * 8;                    // A x4
    int b_row = (lane & 7) + ((lane >> 3) & 1) * 8;                    // B x4.trans
    int b_col = (lane >> 4) * 8;

    for (int kc = 0; kc < 128; kc += BK) {
        // ---- X tile: BM x BK ----
        #pragma unroll
        for (int f = tid; f < BM * (BK / 4); f += 256) {
            int rr = f >> 3, kq = (f & 7) * 4;
            int grow = row0 + rr;
            if (LAYER == 0) {
                float4 v = make_float4(0.f, 0.f, 0.f, 0.f);
                if (grow < NN) v = *(const float4*)(Xext + (size_t)grow * 128 + kc + kq);
                __half h0 = __float2half_rn(v.x), h1 = __float2half_rn(v.y);
                __half h2 = __float2half_rn(v.z), h3 = __float2half_rn(v.w);
                __half l0 = __float2half_rn(v.x - __half2float(h0));
                __half l1 = __float2half_rn(v.y - __half2float(h1));
                __half l2 = __float2half_rn(v.z - __half2float(h2));
                __half l3 = __float2half_rn(v.w - __half2float(h3));
                __half2 H0 = __halves2half2(h0, h1), H1 = __halves2half2(h2, h3);
                __half2 L0 = __halves2half2(l0, l1), L1 = __halves2half2(l2, l3);
                *(uint2*)(XsH + rr * XS + kq) =
                    make_uint2(*(unsigned*)&H0, *(unsigned*)&H1);
                *(uint2*)(XsL + rr * XS + kq) =
                    make_uint2(*(unsigned*)&L0, *(unsigned*)&L1);
            } else {
                uint2 u = make_uint2(0u, 0u);
                if (grow < NN) u = *(const uint2*)(g_agg16 + (size_t)grow * 128 + kc + kq);
                *(uint2*)(XsH + rr * XS + kq) = u;
            }
        }
        // ---- W tile: BK x BN (hi+lo planes, uint4 = 8 halves) ----
        #pragma unroll
        for (int f = tid; f < BK * (BN / 8); f += 256) {
            int kk = f / (BN / 8), nq = (f % (BN / 8)) * 8;
            *(uint4*)(WsH + kk * WS + nq) = *(const uint4*)(Wh + (size_t)(kc + kk) * BN + nq);
            *(uint4*)(WsL + kk * WS + nq) = *(const uint4*)(Wl + (size_t)(kc + kk) * BN + nq);
        }
        __syncthreads();

        #pragma unroll
        for (int k16 = 0; k16 < BK; k16 += 16) {
            unsigned aH[2][4], aL[2][4];
            #pragma unroll
            for (int mt = 0; mt < 2; mt++) {
                unsigned off = (unsigned)(((wm + mt * 16 + a_row) * XS + k16 + a_col) * 2);
                ldsm_x4(aH[mt], xh_base + off);
                if (LAYER == 0) ldsm_x4(aL[mt], xl_base + off);
            }
            #pragma unroll
            for (int np = 0; np < NT / 2; np++) {     // pairs of n-tiles
                unsigned off = (unsigned)(((k16 + b_row) * WS + wn + np * 16 + b_col) * 2);
                unsigned bh[4], bl[4];
                ldsm_x4t(bh, wh_base + off);
                ldsm_x4t(bl, wl_base + off);
                #pragma unroll
                for (int h = 0; h < 2; h++) {         // the two n-tiles in the pair
                    int nt = np * 2 + h;
                    #pragma unroll
                    for (int mt = 0; mt < 2; mt++) {
                        if (LAYER == 0) mma16(acc[mt][nt], aL[mt], bh + 2 * h);
                        mma16(acc[mt][nt], aH[mt], bl + 2 * h);
                        mma16(acc[mt][nt], aH[mt], bh + 2 * h);
                    }
                }
            }
        }
        __syncthreads();
    }

    // epilogue: fp16 store
    int g = lane >> 2, r = lane & 3;
    #pragma unroll
    for (int mt = 0; mt < 2; mt++) {
        int rA = row0 + wm + mt * 16 + g;
        #pragma unroll
        for (int nt = 0; nt < NT; nt++) {
            int col = wn + nt * 8 + 2 * r;
            if (rA < NN)
                *(__half2*)(H + (size_t)rA * BN + col) =
                    __floats2half2_rn(acc[mt][nt][0], acc[mt][nt][1]);
            if (rA + 8 < NN)
                *(__half2*)(H + (size_t)(rA + 8) * BN + col) =
                    __floats2half2_rn(acc[mt][nt][2], acc[mt][nt][3]);
        }
    }
}

// ---------------------------------------------------------------
__device__ __forceinline__ float elu1(float x) { return x > 0.f ? x : expm1f(x); }

__device__ __forceinline__ void acc128(float* acc, uint2 u, float n) {
    float2 f0 = __half22float2(*reinterpret_cast<__half2*>(&u.x));
    float2 f1 = __half22float2(*reinterpret_cast<__half2*>(&u.y));
    acc[0] += f0.x * n; acc[1] += f0.y * n;
    acc[2] += f1.x * n; acc[3] += f1.y * n;
}
__device__ __forceinline__ void acc64(float* acc, unsigned u, float n) {
    float2 f0 = __half22float2(*reinterpret_cast<__half2*>(&u));
    acc[0] += f0.x * n; acc[1] += f0.y * n;
}

template <int D>
__global__ void k_agg(const float* __restrict__ bias, float* __restrict__ outp) {
    int node = (blockIdx.x * blockDim.x + threadIdx.x) >> 5;
    if (node >= NN) return;
    int lane = threadIdx.x & 31;
    constexpr int VL = D / 32;

    const __half* H = (D == DH) ? g_h16 : g_h2_16;

    float acc[VL];
    #pragma unroll
    for (int k = 0; k < VL; k++) acc[k] = 0.f;

    int beg = g_rowptr[node], end = g_rowptr[node + 1];
    int j = beg;
    for (; j + 8 <= end; j += 8) {
        int2 p[8];
        #pragma unroll
        for (int i = 0; i < 8; i++) p[i] = __ldg(&g_epair[j + i]);
        if (D == DH) {
            uint2 u[8];
            #pragma unroll
            for (int i = 0; i < 8; i++)
                u[i] = __ldg((const uint2*)(H + (size_t)p[i].x * D) + lane);
            #pragma unroll
            for (int i = 0; i < 8; i++)
                acc128(acc, u[i], __int_as_float(p[i].y));
        } else {
            unsigned u[8];
            #pragma unroll
            for (int i = 0; i < 8; i++)
                u[i] = __ldg((const unsigned*)(H + (size_t)p[i].x * D) + lane);
            #pragma unroll
            for (int i = 0; i < 8; i++)
                acc64(acc, u[i], __int_as_float(p[i].y));
        }
    }
    for (; j < end; j++) {
        int2 p = __ldg(&g_epair[j]);
        float n = __int_as_float(p.y);
        if (D == DH) {
            uint2 u = __ldg((const uint2*)(H + (size_t)p.x * D) + lane);
            acc128(acc, u, n);
        } else {
            unsigned u = __ldg((const unsigned*)(H + (size_t)p.x * D) + lane);
            acc64(acc, u, n);
        }
    }

    float di = g_dinv[node], d2 = di * di;
    if (D == DH) {
        uint2 us = __ldg((const uint2*)(H + (size_t)node * D) + lane);
        float hv[4] = {0.f, 0.f, 0.f, 0.f};
        acc128(hv, us, d2);
        float4 bv = *(const float4*)(bias + lane * 4);
        float r0 = elu1(acc[0] + hv[0] + bv.x);
        float r1 = elu1(acc[1] + hv[1] + bv.y);
        float r2 = elu1(acc[2] + hv[2] + bv.z);
        float r3 = elu1(acc[3] + hv[3] + bv.w);
        __half2 o0 = __floats2half2_rn(r0, r1);
        __half2 o1 = __floats2half2_rn(r2, r3);
        *((uint2*)(g_agg16 + (size_t)node * D) + lane) =
            make_uint2(*reinterpret_cast<unsigned*>(&o0), *reinterpret_cast<unsigned*>(&o1));
    } else {
        unsigned us = __ldg((const unsigned*)(H + (size_t)node * D) + lane);
        float hv[2] = {0.f, 0.f};
        acc64(hv, us, d2);
        float2 bv = *(const float2*)(bias + lane * 2);
        float2 rr;
        rr.x = elu1(acc[0] + hv[0] + bv.x);
        rr.y = elu1(acc[1] + hv[1] + bv.y);
        *(float2*)(outp + (size_t)node * D + lane * 2) = rr;
    }
}

// ---------------------------------------------------------------
extern "C" void kernel_launch(void* const* d_in, const int* in_sizes, int n_in,
                              void* d_out, int out_size) {
    const float*    x  = (const float*)d_in[0];
    const unsigned* ei = (const unsigned*)d_in[1];
    const float*    W1 = (const float*)d_in[2];
    const float*    b1 = (const float*)d_in[3];
    const float*    W2 = (const float*)d_in[4];
    const float*    b2 = (const float*)d_in[5];
    float*          out = (float*)d_out;

    k_init  <<<(NN + 255) / 256, 256>>>(ei);            // 0
    k_count <<<(NE + 255) / 256, 256>>>(ei);            // 1
    k_wsplit<<<64, 256>>>(W1, W2);                      // 2
    k_mma<DH, 0><<<(NN + 127) / 128, 256>>>(x);         // 3 (profiled slot)
    k_p1    <<<NB, 1024>>>();                           // 4
    k_p2    <<<1, 128>>>();                             // 5
    k_p3    <<<NB, 1024>>>();                           // 6
    k_fill  <<<(NE + 255) / 256, 256>>>(ei);            // 7

    k_agg<DH><<<(NN * 32 + 255) / 256, 256>>>(b1, nullptr);   // 8
    k_mma<DO, 1><<<(NN + 127) / 128, 256>>>(nullptr);         // 9
    k_agg<DO><<<(NN * 32 + 255) / 256, 256>>>(b2, out);       // 10

    (void)in_sizes; (void)n_in; (void)out_size;
}